// round 14
// baseline (speedup 1.0000x reference)
#include <cuda_runtime.h>
#include <math.h>

#define S_  128
#define B_  32
#define H_  512
#define H3  1536
#define V_  10000
#define SB  4096    // S_*B_
#define G   296     // total persistent blocks (2 per SM)
#define RB  224     // recurrence blocks (participate in grid barrier)
#define NTI 157     // logits n-tiles (157*64 = 10048 >= V_)
#define NTM 64      // logits m-tiles (64*64 = 4096 = SB)

// ---------------- static device scratch (no allocations allowed) ----------------
__device__ float g_X   [SB * H_];        // gathered embeddings [m][H], m = t*B + b
__device__ float g_AX0 [SB * H3];        // layer0 x-preacts (+bias) [m][g*H + o]
__device__ float g_tops[SB * H_];        // layer1 outputs per step
__device__ float g_h   [2][B_ * H_];     // current hidden state per layer
__device__ float g_prz0[2][4][B_ * H_];  // layer0 r/z partials [gate][kchunk][b*H+o]
__device__ float g_prz1[2][8][B_ * H_];  // layer1 r/z partials (c<4: x path, c>=4: h path)
__device__ float g_pax2[4][B_ * H_];     // layer1 gate2 x-path partials
__device__ float g_phh [2][4][B_ * H_];  // (r*h)@U2 partials per layer
__device__ int   g_is64;

// barrier / work-queue state (reset each launch by k_reset)
__device__ unsigned g_leaf[8 * 32];           // 8 arrival counters, 128B apart
__device__ volatile unsigned g_gen;           // published barrier generation
__device__ volatile int g_steps_done;         // super-steps completed
__device__ unsigned g_lwork;                  // logits tile work counter

__global__ void k_reset() {
    if (threadIdx.x < 8) g_leaf[threadIdx.x << 5] = 0u;
    if (threadIdx.x == 0) { g_gen = 0u; g_steps_done = 0; g_lwork = 0u; }
}

// Two-level monotonic grid barrier over the RB recurrence blocks.
// q = 1,2,3,... strictly increasing across the kernel. Pure spin (no nanosleep):
// waiters poll one read-only L2 line; master polls 8 spread counter lines.
__device__ __forceinline__ void gridbar(unsigned q, int publish_step) {
    __syncthreads();
    if (threadIdx.x == 0) {
        __threadfence();
        atomicAdd(&g_leaf[(blockIdx.x & 7) << 5], 1u);
        if (blockIdx.x == 0) {
            const unsigned target = (unsigned)RB * q;
            unsigned s;
            do {
                s = 0;
                #pragma unroll
                for (int i = 0; i < 8; i++) s += ((volatile unsigned*)g_leaf)[i << 5];
            } while (s < target);
            __threadfence();
            if (publish_step >= 0) g_steps_done = publish_step;
            g_gen = q;
        } else {
            while (g_gen < q) { }
        }
        __threadfence();
    }
    __syncthreads();
}

// ---------------- token dtype sniff ----------------
// jnp.int64 without x64 enabled materializes as int32. Read the first 2048
// int64 words (16KB, within bounds for BOTH dtypes). If int32, each int64
// word combines two tokens -> >= 2^32 whenever the high token != 0.
__global__ void k_detect(const long long* __restrict__ tok) {
    __shared__ int bad;
    if (threadIdx.x == 0) bad = 0;
    __syncthreads();
    int local = 0;
    for (int j = threadIdx.x; j < 2048; j += blockDim.x) {
        long long v = tok[j];
        if (v < 0 || v >= V_) local = 1;
    }
    if (local) atomicOr(&bad, 1);
    __syncthreads();
    if (threadIdx.x == 0) g_is64 = bad ? 0 : 1;
}

__global__ void k_init(const float* __restrict__ h0) {
    int i = blockIdx.x * blockDim.x + threadIdx.x;
    if (i < 2 * B_ * H_) ((float*)g_h)[i] = h0[i];
}

__global__ void k_gather(const void* __restrict__ tok, const float* __restrict__ emb) {
    int idx = blockIdx.x * blockDim.x + threadIdx.x;   // SB*H/4 threads
    int row = idx >> 7;            // 128 float4 per row
    int c4  = idx & 127;
    int t = g_is64 ? (int)((const long long*)tok)[row]
                   : ((const int*)tok)[row];
    float4 v = ((const float4*)(emb + (size_t)t * H_))[c4];
    ((float4*)(g_X + (size_t)row * H_))[c4] = v;
}

// ---------------- AX0 = X @ Wx[0][g] + bx[0][g]   (NN SGEMM, 64x64x16 tiles) ----------------
__global__ __launch_bounds__(256) void k_ax0(const float* __restrict__ Wx,
                                             const float* __restrict__ bx) {
    const int g  = blockIdx.z;
    const float* Bm = Wx + (size_t)g * H_ * H_;       // [k][n] row-major
    const int m0 = blockIdx.y * 64, n0 = blockIdx.x * 64;
    __shared__ float As[16][68];
    __shared__ float Bs[16][68];
    const int tid = threadIdx.x;
    const int tx = tid & 15, ty = tid >> 4;
    const int am = tid >> 2, ak = (tid & 3) * 4;
    const int bk = tid >> 4, bn = (tid & 15) * 4;
    float acc[4][4] = {};
    for (int k0 = 0; k0 < H_; k0 += 16) {
        float4 a = *(const float4*)(g_X + (size_t)(m0 + am) * H_ + k0 + ak);
        As[ak + 0][am] = a.x; As[ak + 1][am] = a.y;
        As[ak + 2][am] = a.z; As[ak + 3][am] = a.w;
        *(float4*)&Bs[bk][bn] = *(const float4*)(Bm + (size_t)(k0 + bk) * H_ + n0 + bn);
        __syncthreads();
        #pragma unroll
        for (int kk = 0; kk < 16; kk++) {
            float4 a4 = *(const float4*)&As[kk][ty * 4];
            float4 b4 = *(const float4*)&Bs[kk][tx * 4];
            float av[4] = {a4.x, a4.y, a4.z, a4.w};
            float bv[4] = {b4.x, b4.y, b4.z, b4.w};
            #pragma unroll
            for (int i = 0; i < 4; i++)
                #pragma unroll
                for (int j = 0; j < 4; j++)
                    acc[i][j] += av[i] * bv[j];
        }
        __syncthreads();
    }
    #pragma unroll
    for (int i = 0; i < 4; i++)
        #pragma unroll
        for (int j = 0; j < 4; j++) {
            int n = n0 + tx * 4 + j;
            g_AX0[(size_t)(m0 + ty * 4 + i) * H3 + g * H_ + n] = acc[i][j] + bx[g * H_ + n];
        }
}

// ---------------- step-GEMM inner body ----------------
// As: [128 k][36] transposed activations (32 batches). 256 threads =
// 64 o-lanes x 4 groups of 8 batches. K=128. unroll 16 => W-load MLP ~16.
__device__ __forceinline__ void chunk_gemm(const float (*As)[36],
                                           const float* __restrict__ W,
                                           float* __restrict__ outp, int o0) {
    const int tid = threadIdx.x;
    const int ol = tid & 63, bg8 = (tid >> 6) * 8;
    const float* wp = W + o0 + ol;
    float acc[8] = {};
    #pragma unroll 16
    for (int k = 0; k < 128; k++) {
        float w = wp[(size_t)k * H_];
        float4 x0 = *(const float4*)&As[k][bg8];
        float4 x1 = *(const float4*)&As[k][bg8 + 4];
        acc[0] += x0.x * w; acc[1] += x0.y * w; acc[2] += x0.z * w; acc[3] += x0.w * w;
        acc[4] += x1.x * w; acc[5] += x1.y * w; acc[6] += x1.z * w; acc[7] += x1.w * w;
    }
    #pragma unroll
    for (int j = 0; j < 8; j++)
        outp[(size_t)(bg8 + j) * H_ + o0 + ol] = acc[j];
}

__device__ __forceinline__ void fill_As(float (*As)[36], const float* __restrict__ src, int c) {
    for (int idx = threadIdx.x; idx < 4096; idx += 256) {
        int b = idx >> 7, il = idx & 127;
        As[il][b] = src[b * H_ + c * 128 + il];
    }
}

// ---------------- logits 64x64 tile (reads g_tops) ----------------
__device__ __forceinline__ void logits_tile(int m0, int n0,
                                            const float* __restrict__ Wy,
                                            const float* __restrict__ by,
                                            float* __restrict__ out,
                                            float* sh) {
    float (*As)[68] = (float(*)[68])sh;
    float (*Bs)[68] = (float(*)[68])(sh + 16 * 68);
    const int tid = threadIdx.x;
    const int tx = tid & 15, ty = tid >> 4;
    const int am = tid >> 2, ak = (tid & 3) * 4;
    const int bn = tid >> 2, bk = (tid & 3) * 4;
    const int nrow = n0 + bn;
    const bool nok = nrow < V_;
    const float* wyr = Wy + (size_t)(nok ? nrow : 0) * H_;
    float acc[4][4] = {};
    for (int k0 = 0; k0 < H_; k0 += 16) {
        float4 a = *(const float4*)(g_tops + (size_t)(m0 + am) * H_ + k0 + ak);
        As[ak + 0][am] = a.x; As[ak + 1][am] = a.y;
        As[ak + 2][am] = a.z; As[ak + 3][am] = a.w;
        float4 b4 = nok ? *(const float4*)(wyr + k0 + bk) : make_float4(0.f, 0.f, 0.f, 0.f);
        Bs[bk + 0][bn] = b4.x; Bs[bk + 1][bn] = b4.y;
        Bs[bk + 2][bn] = b4.z; Bs[bk + 3][bn] = b4.w;
        __syncthreads();
        #pragma unroll
        for (int kk = 0; kk < 16; kk++) {
            float4 a4 = *(const float4*)&As[kk][ty * 4];
            float4 b4r = *(const float4*)&Bs[kk][tx * 4];
            float av[4] = {a4.x, a4.y, a4.z, a4.w};
            float bv[4] = {b4r.x, b4r.y, b4r.z, b4r.w};
            #pragma unroll
            for (int i = 0; i < 4; i++)
                #pragma unroll
                for (int j = 0; j < 4; j++)
                    acc[i][j] += av[i] * bv[j];
        }
        __syncthreads();
    }
    #pragma unroll
    for (int i = 0; i < 4; i++)
        #pragma unroll
        for (int j = 0; j < 4; j++) {
            int n = n0 + tx * 4 + j;
            if (n < V_)
                out[(size_t)(m0 + ty * 4 + i) * V_ + n] = acc[i][j] + by[n];
        }
}

// ---------------- persistent kernel: recurrence + streamed logits ----------------
__global__ __launch_bounds__(256, 2) void k_recur(const float* __restrict__ Wx,
                                                  const float* __restrict__ bx,
                                                  const float* __restrict__ U,
                                                  const float* __restrict__ Wy,
                                                  const float* __restrict__ by,
                                                  float* __restrict__ out) {
    __shared__ float sh[128 * 36];        // rec: As[128][36]; logits: As16x68+Bs16x68
    __shared__ unsigned s_idx;
    float (*As)[36] = (float(*)[36])sh;

    if (blockIdx.x < RB) {
        unsigned q = 0;
        for (int k = 0; k <= S_; k++) {
            const bool l0 = (k < S_), l1 = (k >= 1);
            const int t0 = k, t1 = k - 1;

            // ---- phase A: r/z pre-activation GEMM partials (+ layer1 ax2 x-path) ----
            {
                const int n0 = l0 ? 64 : 0;
                const int nt = n0 + (l1 ? 160 : 0);
                const int task = blockIdx.x;
                if (task < nt) {
                    const float* W; const float* hsrc; float* outp; int c, ot;
                    if (l0 && task < 64) {               // layer0: g*32 + ot*4 + c
                        int g = task >> 5; ot = (task >> 2) & 7; c = task & 3;
                        hsrc = g_h[0];
                        W = U + ((size_t)g * H_ + c * 128) * H_;          // U[0][g]
                        outp = g_prz0[g][c];
                    } else {
                        int bid = task - n0;
                        if (bid < 128) {                 // layer1 r/z over K=1024
                            int g = bid >> 6; ot = (bid >> 3) & 7; int cf = bid & 7;
                            c = cf & 3;
                            hsrc = (cf < 4) ? g_h[0] : g_h[1];
                            const float* base = (cf < 4) ? (Wx + (size_t)(3 + g) * H_ * H_)
                                                         : (U  + (size_t)(3 + g) * H_ * H_);
                            W = base + (size_t)(c * 128) * H_;
                            outp = g_prz1[g][cf];
                        } else {                         // layer1 ax2 x-path
                            int b2 = bid - 128; ot = b2 >> 2; c = b2 & 3;
                            hsrc = g_h[0];
                            W = Wx + (size_t)5 * H_ * H_ + (size_t)(c * 128) * H_;
                            outp = g_pax2[c];
                        }
                    }
                    fill_As(As, hsrc, c);
                    __syncthreads();
                    chunk_gemm(As, W, outp, ot * 64);
                }
            }
            gridbar(++q, -1);

            // ---- phase B: finalize r, build r*h, GEMM partials vs U[l][2] ----
            {
                const int n0 = l0 ? 32 : 0;
                const int nt = n0 + (l1 ? 32 : 0);
                const int task = blockIdx.x;
                if (task < nt) {
                    const int layer = (l0 && task < 32) ? 0 : 1;
                    const int id = (layer == 0) ? task : task - n0;
                    const int ot = id >> 2, c = id & 3;
                    const float* h = g_h[layer];
                    for (int idx = threadIdx.x; idx < 4096; idx += 256) {
                        int b = idx >> 7, il = idx & 127;
                        int i = c * 128 + il;
                        float pre;
                        if (layer == 0) {
                            pre = g_AX0[(size_t)(t0 * B_ + b) * H3 + i];
                            #pragma unroll
                            for (int cc = 0; cc < 4; cc++) pre += g_prz0[0][cc][b * H_ + i];
                        } else {
                            pre = bx[3 * H_ + i];        // bx[1][0]
                            #pragma unroll
                            for (int cc = 0; cc < 8; cc++) pre += g_prz1[0][cc][b * H_ + i];
                        }
                        float r = 1.0f / (1.0f + expf(-pre));
                        As[il][b] = r * h[b * H_ + i];
                    }
                    __syncthreads();
                    const float* W = U + (size_t)(layer * 3 + 2) * H_ * H_ + (size_t)(c * 128) * H_;
                    chunk_gemm(As, W, g_phh[layer][c], ot * 64);
                }
            }
            gridbar(++q, -1);

            // ---- phase C: finalize z, h_hat, h update ----
            {
                const int total = (l0 ? 16384 : 0) + (l1 ? 16384 : 0);
                for (int idx = blockIdx.x * 256 + threadIdx.x; idx < total; idx += RB * 256) {
                    int e = idx, layer = 0, t = t0;
                    if (!l0 || e >= 16384) { layer = 1; t = t1; if (l0) e -= 16384; }
                    int b = e >> 9, o = e & 511;
                    float zpre, ax2;
                    if (layer == 0) {
                        const float* a = g_AX0 + (size_t)(t * B_ + b) * H3;
                        zpre = a[H_ + o];
                        ax2  = a[2 * H_ + o];
                        #pragma unroll
                        for (int cc = 0; cc < 4; cc++) zpre += g_prz0[1][cc][b * H_ + o];
                    } else {
                        zpre = bx[4 * H_ + o];
                        #pragma unroll
                        for (int cc = 0; cc < 8; cc++) zpre += g_prz1[1][cc][b * H_ + o];
                        ax2 = bx[5 * H_ + o];
                        #pragma unroll
                        for (int cc = 0; cc < 4; cc++) ax2 += g_pax2[cc][b * H_ + o];
                    }
                    float hh = ax2;
                    #pragma unroll
                    for (int cc = 0; cc < 4; cc++) hh += g_phh[layer][cc][b * H_ + o];
                    float z = 1.0f / (1.0f + expf(-zpre));
                    float hprev = g_h[layer][b * H_ + o];
                    float hn = (1.0f - z) * hprev + z * tanhf(hh);
                    g_h[layer][b * H_ + o] = hn;
                    if (layer == 1) g_tops[(size_t)(t * B_ + b) * H_ + o] = hn;
                }
            }
            gridbar(++q, k + 1);   // tops now valid for t <= k-1 (= steps_done - 2)
        }
    }

    // ---- logits drain: workers (blockIdx >= RB) from t=0; rec blocks join after scan ----
    for (;;) {
        if (threadIdx.x == 0) s_idx = atomicAdd(&g_lwork, 1u);
        __syncthreads();
        unsigned idx = s_idx;
        __syncthreads();
        if (idx >= (unsigned)(NTM * NTI)) break;
        int jm = idx / NTI, jn = idx % NTI;
        // tile jm covers t = 2jm, 2jm+1; tops valid for t <= steps_done-2
        // => need steps_done >= 2jm+3. Final publish is S_+1 = 129 = 2*63+3. OK.
        if (threadIdx.x == 0) {
            while (g_steps_done < 2 * jm + 3) { }
        }
        __syncthreads();
        __threadfence();
        logits_tile(jm * 64, jn * 64, Wy, by, out, sh);
        __syncthreads();
    }
}

__global__ void k_final(float* __restrict__ out_tail) {
    int i = blockIdx.x * 256 + threadIdx.x;
    if (i < 2 * B_ * H_) out_tail[i] = ((const float*)g_h)[i];
}

// ---------------- launch ----------------
extern "C" void kernel_launch(void* const* d_in, const int* in_sizes, int n_in,
                              void* d_out, int out_size) {
    const void*  tok = d_in[0];
    const float* h0  = (const float*)d_in[1];
    const float* emb = (const float*)d_in[2];
    const float* Wx  = (const float*)d_in[3];
    const float* bx  = (const float*)d_in[4];
    const float* U   = (const float*)d_in[5];
    const float* Wy  = (const float*)d_in[6];
    const float* by  = (const float*)d_in[7];
    float* out = (float*)d_out;

    k_reset<<<1, 32>>>();
    k_detect<<<1, 256>>>((const long long*)tok);
    k_init<<<(2 * B_ * H_ + 255) / 256, 256>>>(h0);
    k_gather<<<(SB * H_ / 4) / 256, 256>>>(tok, emb);
    k_ax0<<<dim3(8, 64, 3), 256>>>(Wx, bx);

    k_recur<<<G, 256>>>(Wx, bx, U, Wy, by, out);

    k_final<<<(2 * B_ * H_ + 255) / 256, 256>>>(out + (size_t)SB * V_);
}

// round 15
// speedup vs baseline: 1.3495x; 1.3495x over previous
#include <cuda_runtime.h>
#include <math.h>

#define S_  128
#define B_  32
#define H_  512
#define H3  1536
#define V_  10000
#define SB  4096    // S_*B_
#define G   296     // total persistent blocks (2 per SM)
#define RB  224     // recurrence blocks (participate in grid barrier)
#define NTI 157     // logits n-tiles (157*64 = 10048 >= V_)
#define NTM 64      // logits m-tiles (64*64 = 4096 = SB)

// ---------------- static device scratch (no allocations allowed) ----------------
__device__ float g_X   [SB * H_];        // gathered embeddings [m][H], m = t*B + b
__device__ float g_AX0 [SB * H3];        // layer0 x-preacts (+bias) [m][g*H + o]
__device__ float g_tops[SB * H_];        // layer1 outputs per step
__device__ float g_h   [2][B_ * H_];     // current hidden state per layer
__device__ float g_prz0[2][4][B_ * H_];  // layer0 r/z partials [gate][kchunk][b*H+o]
__device__ float g_prz1[2][8][B_ * H_];  // layer1 r/z partials (c<4: x path, c>=4: h path)
__device__ float g_pax2[4][B_ * H_];     // layer1 gate2 x-path partials
__device__ float g_phh [2][4][B_ * H_];  // (r*h)@U2 partials per layer
__device__ int   g_is64;

// barrier / work-queue state (reset each launch by the prologue kernel)
__device__ unsigned g_leaf[8 * 32];           // 8 arrival counters, 128B apart
__device__ volatile unsigned g_gen;           // published barrier generation
__device__ volatile int g_steps_done;         // super-steps completed
__device__ unsigned g_lwork;                  // logits tile work counter

// Two-level monotonic grid barrier over the RB recurrence blocks.
// q = 1,2,3,... strictly increasing across the kernel. nanosleep waiters:
// self-throttled polling, frees issue slots for co-resident logits blocks.
__device__ __forceinline__ void gridbar(unsigned q, int publish_step) {
    __syncthreads();
    if (threadIdx.x == 0) {
        __threadfence();
        atomicAdd(&g_leaf[(blockIdx.x & 7) << 5], 1u);
        if (blockIdx.x == 0) {
            const unsigned target = (unsigned)RB * q;
            for (;;) {
                unsigned s = 0;
                #pragma unroll
                for (int i = 0; i < 8; i++) s += ((volatile unsigned*)g_leaf)[i << 5];
                if (s >= target) break;
                __nanosleep(64);
            }
            __threadfence();
            if (publish_step >= 0) g_steps_done = publish_step;
            g_gen = q;
        } else {
            if (g_gen < q) {
                while (g_gen < q) __nanosleep(64);
            }
        }
        __threadfence();
    }
    __syncthreads();
}

// ---------------- prologue: barrier reset + token dtype sniff + h init ----------------
// jnp.int64 without x64 enabled materializes as int32. Read the first 2048
// int64 words (16KB, within bounds for BOTH dtypes). If int32, each int64
// word combines two tokens -> >= 2^32 whenever the high token != 0.
__global__ void k_prologue(const long long* __restrict__ tok,
                           const float* __restrict__ h0) {
    int i = blockIdx.x * blockDim.x + threadIdx.x;
    if (i < 2 * B_ * H_) ((float*)g_h)[i] = h0[i];
    if (blockIdx.x == 0) {
        if (threadIdx.x < 8) g_leaf[threadIdx.x << 5] = 0u;
        if (threadIdx.x == 0) { g_gen = 0u; g_steps_done = 0; g_lwork = 0u; }
        __shared__ int bad;
        if (threadIdx.x == 0) bad = 0;
        __syncthreads();
        int local = 0;
        for (int j = threadIdx.x; j < 2048; j += blockDim.x) {
            long long v = tok[j];
            if (v < 0 || v >= V_) local = 1;
        }
        if (local) atomicOr(&bad, 1);
        __syncthreads();
        if (threadIdx.x == 0) g_is64 = bad ? 0 : 1;
    }
}

__global__ void k_gather(const void* __restrict__ tok, const float* __restrict__ emb) {
    int idx = blockIdx.x * blockDim.x + threadIdx.x;   // SB*H/4 threads
    int row = idx >> 7;            // 128 float4 per row
    int c4  = idx & 127;
    int t = g_is64 ? (int)((const long long*)tok)[row]
                   : ((const int*)tok)[row];
    float4 v = ((const float4*)(emb + (size_t)t * H_))[c4];
    ((float4*)(g_X + (size_t)row * H_))[c4] = v;
}

// ---------------- AX0 = X @ Wx[0][g] + bx[0][g]   (NN SGEMM, 64x64x16 tiles) ----------------
__global__ __launch_bounds__(256) void k_ax0(const float* __restrict__ Wx,
                                             const float* __restrict__ bx) {
    const int g  = blockIdx.z;
    const float* Bm = Wx + (size_t)g * H_ * H_;       // [k][n] row-major
    const int m0 = blockIdx.y * 64, n0 = blockIdx.x * 64;
    __shared__ float As[16][68];
    __shared__ float Bs[16][68];
    const int tid = threadIdx.x;
    const int tx = tid & 15, ty = tid >> 4;
    const int am = tid >> 2, ak = (tid & 3) * 4;
    const int bk = tid >> 4, bn = (tid & 15) * 4;
    float acc[4][4] = {};
    for (int k0 = 0; k0 < H_; k0 += 16) {
        float4 a = *(const float4*)(g_X + (size_t)(m0 + am) * H_ + k0 + ak);
        As[ak + 0][am] = a.x; As[ak + 1][am] = a.y;
        As[ak + 2][am] = a.z; As[ak + 3][am] = a.w;
        *(float4*)&Bs[bk][bn] = *(const float4*)(Bm + (size_t)(k0 + bk) * H_ + n0 + bn);
        __syncthreads();
        #pragma unroll
        for (int kk = 0; kk < 16; kk++) {
            float4 a4 = *(const float4*)&As[kk][ty * 4];
            float4 b4 = *(const float4*)&Bs[kk][tx * 4];
            float av[4] = {a4.x, a4.y, a4.z, a4.w};
            float bv[4] = {b4.x, b4.y, b4.z, b4.w};
            #pragma unroll
            for (int i = 0; i < 4; i++)
                #pragma unroll
                for (int j = 0; j < 4; j++)
                    acc[i][j] += av[i] * bv[j];
        }
        __syncthreads();
    }
    #pragma unroll
    for (int i = 0; i < 4; i++)
        #pragma unroll
        for (int j = 0; j < 4; j++) {
            int n = n0 + tx * 4 + j;
            g_AX0[(size_t)(m0 + ty * 4 + i) * H3 + g * H_ + n] = acc[i][j] + bx[g * H_ + n];
        }
}

// ---------------- step-GEMM inner body ----------------
// As: [128 k][36] transposed activations (32 batches). 256 threads =
// 64 o-lanes x 4 groups of 8 batches. K=128. unroll 8: MLP ~8 without
// front-batching enough LDGs to inflate cross-CTA L1tex spread (straggler law).
__device__ __forceinline__ void chunk_gemm(const float (*As)[36],
                                           const float* __restrict__ W,
                                           float* __restrict__ outp, int o0) {
    const int tid = threadIdx.x;
    const int ol = tid & 63, bg8 = (tid >> 6) * 8;
    const float* wp = W + o0 + ol;
    float acc[8] = {};
    #pragma unroll 8
    for (int k = 0; k < 128; k++) {
        float w = wp[(size_t)k * H_];
        float4 x0 = *(const float4*)&As[k][bg8];
        float4 x1 = *(const float4*)&As[k][bg8 + 4];
        acc[0] += x0.x * w; acc[1] += x0.y * w; acc[2] += x0.z * w; acc[3] += x0.w * w;
        acc[4] += x1.x * w; acc[5] += x1.y * w; acc[6] += x1.z * w; acc[7] += x1.w * w;
    }
    #pragma unroll
    for (int j = 0; j < 8; j++)
        outp[(size_t)(bg8 + j) * H_ + o0 + ol] = acc[j];
}

__device__ __forceinline__ void fill_As(float (*As)[36], const float* __restrict__ src, int c) {
    for (int idx = threadIdx.x; idx < 4096; idx += 256) {
        int b = idx >> 7, il = idx & 127;
        As[il][b] = src[b * H_ + c * 128 + il];
    }
}

// ---------------- logits 64x64 tile (reads g_tops) ----------------
__device__ __forceinline__ void logits_tile(int m0, int n0,
                                            const float* __restrict__ Wy,
                                            const float* __restrict__ by,
                                            float* __restrict__ out,
                                            float* sh) {
    float (*As)[68] = (float(*)[68])sh;
    float (*Bs)[68] = (float(*)[68])(sh + 16 * 68);
    const int tid = threadIdx.x;
    const int tx = tid & 15, ty = tid >> 4;
    const int am = tid >> 2, ak = (tid & 3) * 4;
    const int bn = tid >> 2, bk = (tid & 3) * 4;
    const int nrow = n0 + bn;
    const bool nok = nrow < V_;
    const float* wyr = Wy + (size_t)(nok ? nrow : 0) * H_;
    float acc[4][4] = {};
    for (int k0 = 0; k0 < H_; k0 += 16) {
        float4 a = *(const float4*)(g_tops + (size_t)(m0 + am) * H_ + k0 + ak);
        As[ak + 0][am] = a.x; As[ak + 1][am] = a.y;
        As[ak + 2][am] = a.z; As[ak + 3][am] = a.w;
        float4 b4 = nok ? *(const float4*)(wyr + k0 + bk) : make_float4(0.f, 0.f, 0.f, 0.f);
        Bs[bk + 0][bn] = b4.x; Bs[bk + 1][bn] = b4.y;
        Bs[bk + 2][bn] = b4.z; Bs[bk + 3][bn] = b4.w;
        __syncthreads();
        #pragma unroll
        for (int kk = 0; kk < 16; kk++) {
            float4 a4 = *(const float4*)&As[kk][ty * 4];
            float4 b4r = *(const float4*)&Bs[kk][tx * 4];
            float av[4] = {a4.x, a4.y, a4.z, a4.w};
            float bv[4] = {b4r.x, b4r.y, b4r.z, b4r.w};
            #pragma unroll
            for (int i = 0; i < 4; i++)
                #pragma unroll
                for (int j = 0; j < 4; j++)
                    acc[i][j] += av[i] * bv[j];
        }
        __syncthreads();
    }
    #pragma unroll
    for (int i = 0; i < 4; i++)
        #pragma unroll
        for (int j = 0; j < 4; j++) {
            int n = n0 + tx * 4 + j;
            if (n < V_)
                out[(size_t)(m0 + ty * 4 + i) * V_ + n] = acc[i][j] + by[n];
        }
}

// ---------------- persistent kernel: recurrence + streamed logits ----------------
__global__ __launch_bounds__(256, 2) void k_recur(const float* __restrict__ Wx,
                                                  const float* __restrict__ bx,
                                                  const float* __restrict__ U,
                                                  const float* __restrict__ Wy,
                                                  const float* __restrict__ by,
                                                  float* __restrict__ out) {
    __shared__ float sh[128 * 36];        // rec: As[128][36]; logits: As16x68+Bs16x68
    __shared__ unsigned s_idx;
    float (*As)[36] = (float(*)[36])sh;

    if (blockIdx.x < RB) {
        unsigned q = 0;
        for (int k = 0; k <= S_; k++) {
            const bool l0 = (k < S_), l1 = (k >= 1);
            const int t0 = k, t1 = k - 1;

            // ---- phase A: r/z pre-activation GEMM partials (+ layer1 ax2 x-path) ----
            {
                const int n0 = l0 ? 64 : 0;
                const int nt = n0 + (l1 ? 160 : 0);
                const int task = blockIdx.x;
                if (task < nt) {
                    const float* W; const float* hsrc; float* outp; int c, ot;
                    if (l0 && task < 64) {               // layer0: g*32 + ot*4 + c
                        int g = task >> 5; ot = (task >> 2) & 7; c = task & 3;
                        hsrc = g_h[0];
                        W = U + ((size_t)g * H_ + c * 128) * H_;          // U[0][g]
                        outp = g_prz0[g][c];
                    } else {
                        int bid = task - n0;
                        if (bid < 128) {                 // layer1 r/z over K=1024
                            int g = bid >> 6; ot = (bid >> 3) & 7; int cf = bid & 7;
                            c = cf & 3;
                            hsrc = (cf < 4) ? g_h[0] : g_h[1];
                            const float* base = (cf < 4) ? (Wx + (size_t)(3 + g) * H_ * H_)
                                                         : (U  + (size_t)(3 + g) * H_ * H_);
                            W = base + (size_t)(c * 128) * H_;
                            outp = g_prz1[g][cf];
                        } else {                         // layer1 ax2 x-path
                            int b2 = bid - 128; ot = b2 >> 2; c = b2 & 3;
                            hsrc = g_h[0];
                            W = Wx + (size_t)5 * H_ * H_ + (size_t)(c * 128) * H_;
                            outp = g_pax2[c];
                        }
                    }
                    fill_As(As, hsrc, c);
                    __syncthreads();
                    chunk_gemm(As, W, outp, ot * 64);
                }
            }
            gridbar(++q, -1);

            // ---- phase B: finalize r, build r*h, GEMM partials vs U[l][2] ----
            {
                const int n0 = l0 ? 32 : 0;
                const int nt = n0 + (l1 ? 32 : 0);
                const int task = blockIdx.x;
                if (task < nt) {
                    const int layer = (l0 && task < 32) ? 0 : 1;
                    const int id = (layer == 0) ? task : task - n0;
                    const int ot = id >> 2, c = id & 3;
                    const float* h = g_h[layer];
                    for (int idx = threadIdx.x; idx < 4096; idx += 256) {
                        int b = idx >> 7, il = idx & 127;
                        int i = c * 128 + il;
                        float pre;
                        if (layer == 0) {
                            pre = g_AX0[(size_t)(t0 * B_ + b) * H3 + i];
                            #pragma unroll
                            for (int cc = 0; cc < 4; cc++) pre += g_prz0[0][cc][b * H_ + i];
                        } else {
                            pre = bx[3 * H_ + i];        // bx[1][0]
                            #pragma unroll
                            for (int cc = 0; cc < 8; cc++) pre += g_prz1[0][cc][b * H_ + i];
                        }
                        float r = 1.0f / (1.0f + expf(-pre));
                        As[il][b] = r * h[b * H_ + i];
                    }
                    __syncthreads();
                    const float* W = U + (size_t)(layer * 3 + 2) * H_ * H_ + (size_t)(c * 128) * H_;
                    chunk_gemm(As, W, g_phh[layer][c], ot * 64);
                }
            }
            gridbar(++q, -1);

            // ---- phase C: finalize z, h_hat, h update ----
            {
                const int total = (l0 ? 16384 : 0) + (l1 ? 16384 : 0);
                for (int idx = blockIdx.x * 256 + threadIdx.x; idx < total; idx += RB * 256) {
                    int e = idx, layer = 0, t = t0;
                    if (!l0 || e >= 16384) { layer = 1; t = t1; if (l0) e -= 16384; }
                    int b = e >> 9, o = e & 511;
                    float zpre, ax2;
                    if (layer == 0) {
                        const float* a = g_AX0 + (size_t)(t * B_ + b) * H3;
                        zpre = a[H_ + o];
                        ax2  = a[2 * H_ + o];
                        #pragma unroll
                        for (int cc = 0; cc < 4; cc++) zpre += g_prz0[1][cc][b * H_ + o];
                    } else {
                        zpre = bx[4 * H_ + o];
                        #pragma unroll
                        for (int cc = 0; cc < 8; cc++) zpre += g_prz1[1][cc][b * H_ + o];
                        ax2 = bx[5 * H_ + o];
                        #pragma unroll
                        for (int cc = 0; cc < 4; cc++) ax2 += g_pax2[cc][b * H_ + o];
                    }
                    float hh = ax2;
                    #pragma unroll
                    for (int cc = 0; cc < 4; cc++) hh += g_phh[layer][cc][b * H_ + o];
                    float z = 1.0f / (1.0f + expf(-zpre));
                    float hprev = g_h[layer][b * H_ + o];
                    float hn = (1.0f - z) * hprev + z * tanhf(hh);
                    g_h[layer][b * H_ + o] = hn;
                    if (layer == 1) g_tops[(size_t)(t * B_ + b) * H_ + o] = hn;
                }
            }
            gridbar(++q, k + 1);   // tops now valid for t <= k-1 (= steps_done - 2)
        }
    }

    // ---- logits drain: workers (blockIdx >= RB) from t=0; rec blocks join after scan ----
    for (;;) {
        if (threadIdx.x == 0) s_idx = atomicAdd(&g_lwork, 1u);
        __syncthreads();
        unsigned idx = s_idx;
        __syncthreads();
        if (idx >= (unsigned)(NTM * NTI)) break;
        int jm = idx / NTI, jn = idx % NTI;
        // tile jm covers t = 2jm, 2jm+1; tops valid for t <= steps_done-2
        // => need steps_done >= 2jm+3. Final publish is S_+1 = 129 = 2*63+3. OK.
        if (threadIdx.x == 0) {
            while (g_steps_done < 2 * jm + 3) __nanosleep(256);
        }
        __syncthreads();
        __threadfence();
        logits_tile(jm * 64, jn * 64, Wy, by, out, sh);
        __syncthreads();
    }
}

__global__ void k_final(float* __restrict__ out_tail) {
    int i = blockIdx.x * 256 + threadIdx.x;
    if (i < 2 * B_ * H_) out_tail[i] = ((const float*)g_h)[i];
}

// ---------------- launch ----------------
extern "C" void kernel_launch(void* const* d_in, const int* in_sizes, int n_in,
                              void* d_out, int out_size) {
    const void*  tok = d_in[0];
    const float* h0  = (const float*)d_in[1];
    const float* emb = (const float*)d_in[2];
    const float* Wx  = (const float*)d_in[3];
    const float* bx  = (const float*)d_in[4];
    const float* U   = (const float*)d_in[5];
    const float* Wy  = (const float*)d_in[6];
    const float* by  = (const float*)d_in[7];
    float* out = (float*)d_out;

    // launch order chosen so k_recur is the 4th launch (ncu's profiled slot)
    k_prologue<<<(2 * B_ * H_ + 255) / 256, 256>>>((const long long*)tok, h0);
    k_gather<<<(SB * H_ / 4) / 256, 256>>>(tok, emb);
    k_ax0<<<dim3(8, 64, 3), 256>>>(Wx, bx);

    k_recur<<<G, 256>>>(Wx, bx, U, Wy, by, out);

    k_final<<<(2 * B_ * H_ + 255) / 256, 256>>>(out + (size_t)SB * V_);
}

// round 16
// speedup vs baseline: 1.4629x; 1.0841x over previous
#include <cuda_runtime.h>
#include <math.h>

#define S_  128
#define B_  32
#define H_  512
#define H3  1536
#define V_  10000
#define SB  4096    // S_*B_
#define G   296     // total persistent blocks (2 per SM)
#define RB  224     // recurrence blocks (participate in grid barrier)
#define NTI 157     // logits n-tiles (157*64 = 10048 >= V_)
#define NTM 64      // logits m-tiles (64*64 = 4096 = SB)

// ---------------- static device scratch (no allocations allowed) ----------------
__device__ float g_X   [SB * H_];        // gathered embeddings [m][H], m = t*B + b
__device__ float g_AX0 [SB * H3];        // layer0 x-preacts (+bias) [m][g*H + o]
__device__ float g_tops[SB * H_];        // layer1 outputs per step
__device__ float g_h   [2][B_ * H_];     // current hidden state per layer
__device__ float g_prz0[2][4][B_ * H_];  // layer0 r/z partials [gate][kchunk][b*H+o]
__device__ float g_prz1[2][8][B_ * H_];  // layer1 r/z partials (c<4: x path, c>=4: h path)
__device__ float g_pax2[4][B_ * H_];     // layer1 gate2 x-path partials
__device__ float g_phh [2][4][B_ * H_];  // (r*h)@U2 partials per layer
__device__ int   g_is64;

// barrier / work-queue state (reset each launch by the prologue kernel)
__device__ unsigned g_leaf[8 * 32];           // 8 arrival counters, 128B apart
__device__ volatile unsigned g_gen;           // published barrier generation
__device__ volatile int g_steps_done;         // super-steps completed
__device__ unsigned g_lwork;                  // logits tile work counter

// Two-level monotonic grid barrier over the RB recurrence blocks.
// q = 1,2,3,... strictly increasing across the kernel. nanosleep waiters:
// self-throttled polling, frees issue slots for co-resident logits blocks.
__device__ __forceinline__ void gridbar(unsigned q, int publish_step) {
    __syncthreads();
    if (threadIdx.x == 0) {
        __threadfence();
        atomicAdd(&g_leaf[(blockIdx.x & 7) << 5], 1u);
        if (blockIdx.x == 0) {
            const unsigned target = (unsigned)RB * q;
            for (;;) {
                unsigned s = 0;
                #pragma unroll
                for (int i = 0; i < 8; i++) s += ((volatile unsigned*)g_leaf)[i << 5];
                if (s >= target) break;
                __nanosleep(64);
            }
            __threadfence();
            if (publish_step >= 0) g_steps_done = publish_step;
            g_gen = q;
        } else {
            if (g_gen < q) {
                while (g_gen < q) __nanosleep(64);
            }
        }
        __threadfence();
    }
    __syncthreads();
}

// ---------------- prologue: barrier reset + token dtype sniff + h init ----------------
// jnp.int64 without x64 enabled materializes as int32. Read the first 2048
// int64 words (16KB, within bounds for BOTH dtypes). If int32, each int64
// word combines two tokens -> >= 2^32 whenever the high token != 0.
__global__ void k_prologue(const long long* __restrict__ tok,
                           const float* __restrict__ h0) {
    int i = blockIdx.x * blockDim.x + threadIdx.x;
    if (i < 2 * B_ * H_) ((float*)g_h)[i] = h0[i];
    if (blockIdx.x == 0) {
        if (threadIdx.x < 8) g_leaf[threadIdx.x << 5] = 0u;
        if (threadIdx.x == 0) { g_gen = 0u; g_steps_done = 0; g_lwork = 0u; }
        __shared__ int bad;
        if (threadIdx.x == 0) bad = 0;
        __syncthreads();
        int local = 0;
        for (int j = threadIdx.x; j < 2048; j += blockDim.x) {
            long long v = tok[j];
            if (v < 0 || v >= V_) local = 1;
        }
        if (local) atomicOr(&bad, 1);
        __syncthreads();
        if (threadIdx.x == 0) g_is64 = bad ? 0 : 1;
    }
}

__global__ void k_gather(const void* __restrict__ tok, const float* __restrict__ emb) {
    int idx = blockIdx.x * blockDim.x + threadIdx.x;   // SB*H/4 threads
    int row = idx >> 7;            // 128 float4 per row
    int c4  = idx & 127;
    int t = g_is64 ? (int)((const long long*)tok)[row]
                   : ((const int*)tok)[row];
    float4 v = ((const float4*)(emb + (size_t)t * H_))[c4];
    ((float4*)(g_X + (size_t)row * H_))[c4] = v;
}

// ---------------- AX0 = X @ Wx[0][g] + bx[0][g]   (NN SGEMM, 64x64x16 tiles) ----------------
__global__ __launch_bounds__(256) void k_ax0(const float* __restrict__ Wx,
                                             const float* __restrict__ bx) {
    const int g  = blockIdx.z;
    const float* Bm = Wx + (size_t)g * H_ * H_;       // [k][n] row-major
    const int m0 = blockIdx.y * 64, n0 = blockIdx.x * 64;
    __shared__ float As[16][68];
    __shared__ float Bs[16][68];
    const int tid = threadIdx.x;
    const int tx = tid & 15, ty = tid >> 4;
    const int am = tid >> 2, ak = (tid & 3) * 4;
    const int bk = tid >> 4, bn = (tid & 15) * 4;
    float acc[4][4] = {};
    for (int k0 = 0; k0 < H_; k0 += 16) {
        float4 a = *(const float4*)(g_X + (size_t)(m0 + am) * H_ + k0 + ak);
        As[ak + 0][am] = a.x; As[ak + 1][am] = a.y;
        As[ak + 2][am] = a.z; As[ak + 3][am] = a.w;
        *(float4*)&Bs[bk][bn] = *(const float4*)(Bm + (size_t)(k0 + bk) * H_ + n0 + bn);
        __syncthreads();
        #pragma unroll
        for (int kk = 0; kk < 16; kk++) {
            float4 a4 = *(const float4*)&As[kk][ty * 4];
            float4 b4 = *(const float4*)&Bs[kk][tx * 4];
            float av[4] = {a4.x, a4.y, a4.z, a4.w};
            float bv[4] = {b4.x, b4.y, b4.z, b4.w};
            #pragma unroll
            for (int i = 0; i < 4; i++)
                #pragma unroll
                for (int j = 0; j < 4; j++)
                    acc[i][j] += av[i] * bv[j];
        }
        __syncthreads();
    }
    #pragma unroll
    for (int i = 0; i < 4; i++)
        #pragma unroll
        for (int j = 0; j < 4; j++) {
            int n = n0 + tx * 4 + j;
            g_AX0[(size_t)(m0 + ty * 4 + i) * H3 + g * H_ + n] = acc[i][j] + bx[g * H_ + n];
        }
}

// ---------------- step-GEMM inner body ----------------
// As: [128 k][36] transposed activations (32 batches). 256 threads =
// 64 o-lanes x 4 groups of 8 batches. K=128. unroll 8: MLP ~8 without
// front-batching enough LDGs to inflate cross-CTA L1tex spread (straggler law).
__device__ __forceinline__ void chunk_gemm(const float (*As)[36],
                                           const float* __restrict__ W,
                                           float* __restrict__ outp, int o0) {
    const int tid = threadIdx.x;
    const int ol = tid & 63, bg8 = (tid >> 6) * 8;
    const float* wp = W + o0 + ol;
    float acc[8] = {};
    #pragma unroll 8
    for (int k = 0; k < 128; k++) {
        float w = wp[(size_t)k * H_];
        float4 x0 = *(const float4*)&As[k][bg8];
        float4 x1 = *(const float4*)&As[k][bg8 + 4];
        acc[0] += x0.x * w; acc[1] += x0.y * w; acc[2] += x0.z * w; acc[3] += x0.w * w;
        acc[4] += x1.x * w; acc[5] += x1.y * w; acc[6] += x1.z * w; acc[7] += x1.w * w;
    }
    #pragma unroll
    for (int j = 0; j < 8; j++)
        outp[(size_t)(bg8 + j) * H_ + o0 + ol] = acc[j];
}

__device__ __forceinline__ void fill_As(float (*As)[36], const float* __restrict__ src, int c) {
    for (int idx = threadIdx.x; idx < 4096; idx += 256) {
        int b = idx >> 7, il = idx & 127;
        As[il][b] = src[b * H_ + c * 128 + il];
    }
}

// ---------------- logits 64x64 tile (reads g_tops) ----------------
__device__ __forceinline__ void logits_tile(int m0, int n0,
                                            const float* __restrict__ Wy,
                                            const float* __restrict__ by,
                                            float* __restrict__ out,
                                            float* sh) {
    float (*As)[68] = (float(*)[68])sh;
    float (*Bs)[68] = (float(*)[68])(sh + 16 * 68);
    const int tid = threadIdx.x;
    const int tx = tid & 15, ty = tid >> 4;
    const int am = tid >> 2, ak = (tid & 3) * 4;
    const int bn = tid >> 2, bk = (tid & 3) * 4;
    const int nrow = n0 + bn;
    const bool nok = nrow < V_;
    const float* wyr = Wy + (size_t)(nok ? nrow : 0) * H_;
    float acc[4][4] = {};
    for (int k0 = 0; k0 < H_; k0 += 16) {
        float4 a = *(const float4*)(g_tops + (size_t)(m0 + am) * H_ + k0 + ak);
        As[ak + 0][am] = a.x; As[ak + 1][am] = a.y;
        As[ak + 2][am] = a.z; As[ak + 3][am] = a.w;
        float4 b4 = nok ? *(const float4*)(wyr + k0 + bk) : make_float4(0.f, 0.f, 0.f, 0.f);
        Bs[bk + 0][bn] = b4.x; Bs[bk + 1][bn] = b4.y;
        Bs[bk + 2][bn] = b4.z; Bs[bk + 3][bn] = b4.w;
        __syncthreads();
        #pragma unroll
        for (int kk = 0; kk < 16; kk++) {
            float4 a4 = *(const float4*)&As[kk][ty * 4];
            float4 b4r = *(const float4*)&Bs[kk][tx * 4];
            float av[4] = {a4.x, a4.y, a4.z, a4.w};
            float bv[4] = {b4r.x, b4r.y, b4r.z, b4r.w};
            #pragma unroll
            for (int i = 0; i < 4; i++)
                #pragma unroll
                for (int j = 0; j < 4; j++)
                    acc[i][j] += av[i] * bv[j];
        }
        __syncthreads();
    }
    #pragma unroll
    for (int i = 0; i < 4; i++)
        #pragma unroll
        for (int j = 0; j < 4; j++) {
            int n = n0 + tx * 4 + j;
            if (n < V_)
                out[(size_t)(m0 + ty * 4 + i) * V_ + n] = acc[i][j] + by[n];
        }
}

// ---------------- persistent kernel: recurrence + streamed logits ----------------
__global__ __launch_bounds__(256, 2) void k_recur(const float* __restrict__ Wx,
                                                  const float* __restrict__ bx,
                                                  const float* __restrict__ U,
                                                  const float* __restrict__ Wy,
                                                  const float* __restrict__ by,
                                                  float* __restrict__ out) {
    __shared__ float sh[128 * 36];        // rec: As[128][36]; logits: As16x68+Bs16x68
    __shared__ unsigned s_idx;
    float (*As)[36] = (float(*)[36])sh;

    if (blockIdx.x < RB) {
        unsigned q = 0;
        for (int k = 0; k <= S_; k++) {
            const bool l0 = (k < S_), l1 = (k >= 1);
            const int t0 = k, t1 = k - 1;

            // ---- phase A: r/z pre-activation GEMM partials (+ layer1 ax2 x-path) ----
            {
                const int n0 = l0 ? 64 : 0;
                const int nt = n0 + (l1 ? 160 : 0);
                const int task = blockIdx.x;
                if (task < nt) {
                    const float* W; const float* hsrc; float* outp; int c, ot;
                    if (l0 && task < 64) {               // layer0: g*32 + ot*4 + c
                        int g = task >> 5; ot = (task >> 2) & 7; c = task & 3;
                        hsrc = g_h[0];
                        W = U + ((size_t)g * H_ + c * 128) * H_;          // U[0][g]
                        outp = g_prz0[g][c];
                    } else {
                        int bid = task - n0;
                        if (bid < 128) {                 // layer1 r/z over K=1024
                            int g = bid >> 6; ot = (bid >> 3) & 7; int cf = bid & 7;
                            c = cf & 3;
                            hsrc = (cf < 4) ? g_h[0] : g_h[1];
                            const float* base = (cf < 4) ? (Wx + (size_t)(3 + g) * H_ * H_)
                                                         : (U  + (size_t)(3 + g) * H_ * H_);
                            W = base + (size_t)(c * 128) * H_;
                            outp = g_prz1[g][cf];
                        } else {                         // layer1 ax2 x-path
                            int b2 = bid - 128; ot = b2 >> 2; c = b2 & 3;
                            hsrc = g_h[0];
                            W = Wx + (size_t)5 * H_ * H_ + (size_t)(c * 128) * H_;
                            outp = g_pax2[c];
                        }
                    }
                    fill_As(As, hsrc, c);
                    __syncthreads();
                    chunk_gemm(As, W, outp, ot * 64);
                }
            }
            gridbar(++q, -1);

            // ---- phase B: finalize r, build r*h, GEMM partials vs U[l][2] ----
            {
                const int n0 = l0 ? 32 : 0;
                const int nt = n0 + (l1 ? 32 : 0);
                const int task = blockIdx.x;
                if (task < nt) {
                    const int layer = (l0 && task < 32) ? 0 : 1;
                    const int id = (layer == 0) ? task : task - n0;
                    const int ot = id >> 2, c = id & 3;
                    const float* h = g_h[layer];
                    for (int idx = threadIdx.x; idx < 4096; idx += 256) {
                        int b = idx >> 7, il = idx & 127;
                        int i = c * 128 + il;
                        float pre;
                        if (layer == 0) {
                            pre = g_AX0[(size_t)(t0 * B_ + b) * H3 + i];
                            #pragma unroll
                            for (int cc = 0; cc < 4; cc++) pre += g_prz0[0][cc][b * H_ + i];
                        } else {
                            pre = bx[3 * H_ + i];        // bx[1][0]
                            #pragma unroll
                            for (int cc = 0; cc < 8; cc++) pre += g_prz1[0][cc][b * H_ + i];
                        }
                        float r = 1.0f / (1.0f + expf(-pre));
                        As[il][b] = r * h[b * H_ + i];
                    }
                    __syncthreads();
                    const float* W = U + (size_t)(layer * 3 + 2) * H_ * H_ + (size_t)(c * 128) * H_;
                    chunk_gemm(As, W, g_phh[layer][c], ot * 64);
                }
            }
            gridbar(++q, -1);

            // ---- phase C: finalize z, h_hat, h update ----
            {
                const int total = (l0 ? 16384 : 0) + (l1 ? 16384 : 0);
                for (int idx = blockIdx.x * 256 + threadIdx.x; idx < total; idx += RB * 256) {
                    int e = idx, layer = 0, t = t0;
                    if (!l0 || e >= 16384) { layer = 1; t = t1; if (l0) e -= 16384; }
                    int b = e >> 9, o = e & 511;
                    float zpre, ax2;
                    if (layer == 0) {
                        const float* a = g_AX0 + (size_t)(t * B_ + b) * H3;
                        zpre = a[H_ + o];
                        ax2  = a[2 * H_ + o];
                        #pragma unroll
                        for (int cc = 0; cc < 4; cc++) zpre += g_prz0[1][cc][b * H_ + o];
                    } else {
                        zpre = bx[4 * H_ + o];
                        #pragma unroll
                        for (int cc = 0; cc < 8; cc++) zpre += g_prz1[1][cc][b * H_ + o];
                        ax2 = bx[5 * H_ + o];
                        #pragma unroll
                        for (int cc = 0; cc < 4; cc++) ax2 += g_pax2[cc][b * H_ + o];
                    }
                    float hh = ax2;
                    #pragma unroll
                    for (int cc = 0; cc < 4; cc++) hh += g_phh[layer][cc][b * H_ + o];
                    float z = 1.0f / (1.0f + expf(-zpre));
                    float hprev = g_h[layer][b * H_ + o];
                    float hn = (1.0f - z) * hprev + z * tanhf(hh);
                    g_h[layer][b * H_ + o] = hn;
                    if (layer == 1) g_tops[(size_t)(t * B_ + b) * H_ + o] = hn;
                }
            }
            gridbar(++q, k + 1);   // tops now valid for t <= k-1 (= steps_done - 2)
        }
    }

    // ---- logits drain: workers (blockIdx >= RB) from t=0; rec blocks join after scan ----
    for (;;) {
        if (threadIdx.x == 0) s_idx = atomicAdd(&g_lwork, 1u);
        __syncthreads();
        unsigned idx = s_idx;
        __syncthreads();
        if (idx >= (unsigned)(NTM * NTI)) break;
        int jm = idx / NTI, jn = idx % NTI;
        // tile jm covers t = 2jm, 2jm+1; tops valid for t <= steps_done-2
        // => need steps_done >= 2jm+3. Final publish is S_+1 = 129 = 2*63+3. OK.
        if (threadIdx.x == 0) {
            while (g_steps_done < 2 * jm + 3) __nanosleep(256);
        }
        __syncthreads();
        __threadfence();
        logits_tile(jm * 64, jn * 64, Wy, by, out, sh);
        __syncthreads();
    }
}

__global__ void k_final(float* __restrict__ out_tail) {
    int i = blockIdx.x * 256 + threadIdx.x;
    if (i < 2 * B_ * H_) out_tail[i] = ((const float*)g_h)[i];
}

// ---------------- launch ----------------
extern "C" void kernel_launch(void* const* d_in, const int* in_sizes, int n_in,
                              void* d_out, int out_size) {
    const void*  tok = d_in[0];
    const float* h0  = (const float*)d_in[1];
    const float* emb = (const float*)d_in[2];
    const float* Wx  = (const float*)d_in[3];
    const float* bx  = (const float*)d_in[4];
    const float* U   = (const float*)d_in[5];
    const float* Wy  = (const float*)d_in[6];
    const float* by  = (const float*)d_in[7];
    float* out = (float*)d_out;

    // launch order chosen so k_recur is the 4th launch (ncu's profiled slot)
    k_prologue<<<(2 * B_ * H_ + 255) / 256, 256>>>((const long long*)tok, h0);
    k_gather<<<(SB * H_ / 4) / 256, 256>>>(tok, emb);
    k_ax0<<<dim3(8, 64, 3), 256>>>(Wx, bx);

    k_recur<<<G, 256>>>(Wx, bx, U, Wy, by, out);

    k_final<<<(2 * B_ * H_ + 255) / 256, 256>>>(out + (size_t)SB * V_);
}